// round 2
// baseline (speedup 1.0000x reference)
#include <cuda_runtime.h>
#include <math.h>

#define N_NODES  100000
#define N_EDGES  1600000
#define NFEAT    128
#define NHID     64
#define NCLUST   20
#define ALPHA    0.2f

// Scratch (static device arrays are allowed; cudaMalloc is not)
__device__ float g_support[(size_t)N_NODES * NHID];
__device__ float g_deg[N_NODES];
__device__ float g_dinv[N_NODES];
__device__ int   g_idx64;   // 1 if edge_index is int64, 0 if int32

// ---------------------------------------------------------------------------
// K0: detect edge_index dtype. JAX with x64 disabled silently downcasts the
// requested int64 to int32. Reading int32 data as int64 packs two indices per
// word: the high 32 bits are the NEXT index (nonzero w.p. 1-1e-5 per probe).
// Genuine int64 indices (< 100000) always have zero high words.
// ---------------------------------------------------------------------------
__global__ void k_detect(const void* ei) {
    const unsigned long long* p = (const unsigned long long*)ei;
    int is64 = 1;
    for (int i = 0; i < 16; i++)
        if (p[i] >> 32) { is64 = 0; break; }
    g_idx64 = is64;
}

__device__ __forceinline__ int load_idx(const void* ei, size_t i) {
    return g_idx64 ? (int)((const long long*)ei)[i] : ((const int*)ei)[i];
}

// ---------------------------------------------------------------------------
// K1: support = x @ W (100000x128 @ 128x64); also deg[row] = 1.0 (self loop).
// 128 threads/block compute a 64x64 tile; 8x4 microtile per thread.
// ---------------------------------------------------------------------------
__global__ __launch_bounds__(128) void k_gemm(const float* __restrict__ x,
                                              const float* __restrict__ W) {
    __shared__ float xs[64 * 65];   // pad to break bank conflicts
    __shared__ float Ws[64 * 64];
    const int tid  = threadIdx.x;
    const int row0 = blockIdx.x * 64;

    if (tid < 64 && row0 + tid < N_NODES) g_deg[row0 + tid] = 1.0f;

    const int cg = (tid & 15) * 4;   // col group: 0..60
    const int rg = (tid >> 4) * 8;   // row group: 0..56

    float acc[8][4];
#pragma unroll
    for (int i = 0; i < 8; i++)
#pragma unroll
        for (int j = 0; j < 4; j++) acc[i][j] = 0.0f;

    for (int kc = 0; kc < NFEAT; kc += 64) {
#pragma unroll
        for (int it = 0; it < 8; it++) {
            int idx = tid + it * 128;      // 1024 float4 slots
            int r   = idx >> 4;
            int c4  = (idx & 15) * 4;
            float4 v = make_float4(0.f, 0.f, 0.f, 0.f);
            int gr = row0 + r;
            if (gr < N_NODES)
                v = *(const float4*)(x + (size_t)gr * NFEAT + kc + c4);
            xs[r * 65 + c4 + 0] = v.x;
            xs[r * 65 + c4 + 1] = v.y;
            xs[r * 65 + c4 + 2] = v.z;
            xs[r * 65 + c4 + 3] = v.w;
        }
        {
            const float4* Wg = (const float4*)(W + (size_t)kc * NHID);
            float4* Ws4 = (float4*)Ws;
#pragma unroll
            for (int it = 0; it < 8; it++)
                Ws4[tid + it * 128] = Wg[tid + it * 128];
        }
        __syncthreads();

#pragma unroll 4
        for (int k = 0; k < 64; k++) {
            float4 bb = *(const float4*)(Ws + k * 64 + cg);
#pragma unroll
            for (int i = 0; i < 8; i++) {
                float a = xs[(rg + i) * 65 + k];
                acc[i][0] += a * bb.x;
                acc[i][1] += a * bb.y;
                acc[i][2] += a * bb.z;
                acc[i][3] += a * bb.w;
            }
        }
        __syncthreads();
    }

#pragma unroll
    for (int i = 0; i < 8; i++) {
        int gr = row0 + rg + i;
        if (gr < N_NODES)
            *(float4*)(g_support + (size_t)gr * NHID + cg) =
                make_float4(acc[i][0], acc[i][1], acc[i][2], acc[i][3]);
    }
}

// ---------------------------------------------------------------------------
// K2: deg[dst] += edge_weight
// ---------------------------------------------------------------------------
__global__ __launch_bounds__(256) void k_deg(const void* __restrict__ ei,
                                             const float* __restrict__ ew) {
    int e = blockIdx.x * 256 + threadIdx.x;
    if (e < N_EDGES) {
        int dst = load_idx(ei, (size_t)N_EDGES + e);
        atomicAdd(&g_deg[dst], ew[e]);
    }
}

// ---------------------------------------------------------------------------
// K3a: dinv = rsqrt(deg)
// ---------------------------------------------------------------------------
__global__ __launch_bounds__(256) void k_dinv() {
    int i = blockIdx.x * 256 + threadIdx.x;
    if (i < N_NODES) {
        float d = g_deg[i];
        g_dinv[i] = (d > 0.0f) ? rsqrtf(d) : 0.0f;
    }
}

// ---------------------------------------------------------------------------
// K3b: z[i,:] = dinv[i]^2 * support[i,:]  (self-loop term, initializes d_out)
// ---------------------------------------------------------------------------
__global__ __launch_bounds__(256) void k_initz(float* __restrict__ outz) {
    int idx = blockIdx.x * 256 + threadIdx.x;     // float4 index
    if (idx < N_NODES * (NHID / 4)) {
        int node = idx >> 4;                      // 16 float4 per node
        float di = g_dinv[node];
        float s  = di * di;
        float4 v = ((const float4*)g_support)[idx];
        v.x *= s; v.y *= s; v.z *= s; v.w *= s;
        ((float4*)outz)[idx] = v;
    }
}

// ---------------------------------------------------------------------------
// K4: edge scatter. One warp per edge, 2 floats per lane.
// z[dst,:] += dinv[src]*w*dinv[dst] * support[src,:]
// ---------------------------------------------------------------------------
__global__ __launch_bounds__(256) void k_scatter(const void* __restrict__ ei,
                                                 const float* __restrict__ ew,
                                                 float* __restrict__ outz) {
    int e = blockIdx.x * 8 + (threadIdx.x >> 5);
    if (e >= N_EDGES) return;
    int lane = threadIdx.x & 31;

    int src = load_idx(ei, e);
    int dst = load_idx(ei, (size_t)N_EDGES + e);
    float norm = g_dinv[src] * ew[e] * g_dinv[dst];

    float2 s = ((const float2*)g_support)[(size_t)src * 32 + lane];
    float* o = outz + (size_t)dst * NHID + 2 * lane;
    atomicAdd(o,     s.x * norm);
    atomicAdd(o + 1, s.y * norm);
}

// ---------------------------------------------------------------------------
// K5: z += b; q = student-t soft assignment, row-normalized. One warp/node.
// ---------------------------------------------------------------------------
__global__ __launch_bounds__(128) void k_head(const float* __restrict__ b,
                                              const float* __restrict__ mu,
                                              float* __restrict__ out) {
    __shared__ float smu[NCLUST * NHID];
    for (int i = threadIdx.x; i < NCLUST * NHID; i += 128)
        smu[i] = mu[i];
    __syncthreads();

    int node = blockIdx.x * 4 + (threadIdx.x >> 5);
    int lane = threadIdx.x & 31;
    if (node >= N_NODES) return;

    float2 z  = ((float2*)out)[(size_t)node * 32 + lane];
    float2 bb = ((const float2*)b)[lane];
    z.x += bb.x; z.y += bb.y;
    ((float2*)out)[(size_t)node * 32 + lane] = z;

    float p[NCLUST];
#pragma unroll
    for (int k = 0; k < NCLUST; k++) {
        float dx = z.x - smu[k * NHID + 2 * lane];
        float dy = z.y - smu[k * NHID + 2 * lane + 1];
        p[k] = dx * dx + dy * dy;
    }
#pragma unroll
    for (int off = 16; off > 0; off >>= 1) {
#pragma unroll
        for (int k = 0; k < NCLUST; k++)
            p[k] += __shfl_xor_sync(0xffffffff, p[k], off);
    }
    float q[NCLUST];
    float qs = 0.0f;
#pragma unroll
    for (int k = 0; k < NCLUST; k++) {
        float t = 1.0f / (1.0f + p[k] * (1.0f / ALPHA) + 1e-8f);
        q[k] = __powf(t, ALPHA + 1.0f);   // /2 cancels under normalization
        qs += q[k];
    }
    float inv = 1.0f / qs;
    if (lane < NCLUST)
        out[(size_t)N_NODES * NHID + (size_t)node * NCLUST + lane] = q[lane] * inv;
}

// ---------------------------------------------------------------------------
extern "C" void kernel_launch(void* const* d_in, const int* in_sizes, int n_in,
                              void* d_out, int out_size) {
    const float* x  = (const float*)d_in[0];
    const void*  ei = d_in[1];
    const float* ew = (const float*)d_in[2];
    const float* W  = (const float*)d_in[3];
    const float* b  = (const float*)d_in[4];
    const float* mu = (const float*)d_in[5];
    float* out = (float*)d_out;

    k_detect<<<1, 1>>>(ei);
    k_gemm<<<(N_NODES + 63) / 64, 128>>>(x, W);
    k_deg<<<(N_EDGES + 255) / 256, 256>>>(ei, ew);
    k_dinv<<<(N_NODES + 255) / 256, 256>>>();
    k_initz<<<(N_NODES * (NHID / 4) + 255) / 256, 256>>>(out);
    k_scatter<<<(N_EDGES + 7) / 8, 256>>>(ei, ew, out);
    k_head<<<(N_NODES + 3) / 4, 128>>>(b, mu, out);
}

// round 3
// speedup vs baseline: 1.5148x; 1.5148x over previous
#include <cuda_runtime.h>
#include <math.h>

#define N_NODES  100000
#define N_EDGES  1600000
#define NFEAT    128
#define NHID     64
#define NCLUST   20
#define ALPHA    0.2f

#define SCAN_BS     512
#define SCAN_BLOCKS ((N_NODES + SCAN_BS - 1) / SCAN_BS)   // 196

// Scratch (static device arrays; no cudaMalloc allowed)
__device__ float g_support[(size_t)N_NODES * NHID];
__device__ float g_deg[N_NODES];
__device__ float g_dinv[N_NODES];
__device__ int   g_cnt[N_NODES];
__device__ int   g_rowptr[N_NODES];
__device__ int   g_cursor[N_NODES];
__device__ int   g_blksum[SCAN_BLOCKS];
__device__ int   g_blkoff[SCAN_BLOCKS];
__device__ uint2 g_bin[N_EDGES];          // {src, bitcast(dinv[src]*w)}
__device__ int   g_idx64;

// ---------------------------------------------------------------------------
// K0: detect edge_index dtype (JAX x64-disabled silently emits int32).
// ---------------------------------------------------------------------------
__global__ void k_detect(const void* ei) {
    const unsigned long long* p = (const unsigned long long*)ei;
    int is64 = 1;
    for (int i = 0; i < 16; i++)
        if (p[i] >> 32) { is64 = 0; break; }
    g_idx64 = is64;
}

__device__ __forceinline__ int load_idx(const void* ei, size_t i) {
    return g_idx64 ? (int)((const long long*)ei)[i] : ((const int*)ei)[i];
}

// ---------------------------------------------------------------------------
// K1: support = x @ W; also reset deg=1 (self loop) and cnt=0.
// ---------------------------------------------------------------------------
__global__ __launch_bounds__(128) void k_gemm(const float* __restrict__ x,
                                              const float* __restrict__ W) {
    __shared__ float xs[64 * 65];
    __shared__ float Ws[64 * 64];
    const int tid  = threadIdx.x;
    const int row0 = blockIdx.x * 64;

    if (tid < 64 && row0 + tid < N_NODES) {
        g_deg[row0 + tid] = 1.0f;
        g_cnt[row0 + tid] = 0;
    }

    const int cg = (tid & 15) * 4;
    const int rg = (tid >> 4) * 8;

    float acc[8][4];
#pragma unroll
    for (int i = 0; i < 8; i++)
#pragma unroll
        for (int j = 0; j < 4; j++) acc[i][j] = 0.0f;

    for (int kc = 0; kc < NFEAT; kc += 64) {
#pragma unroll
        for (int it = 0; it < 8; it++) {
            int idx = tid + it * 128;
            int r   = idx >> 4;
            int c4  = (idx & 15) * 4;
            float4 v = make_float4(0.f, 0.f, 0.f, 0.f);
            int gr = row0 + r;
            if (gr < N_NODES)
                v = *(const float4*)(x + (size_t)gr * NFEAT + kc + c4);
            xs[r * 65 + c4 + 0] = v.x;
            xs[r * 65 + c4 + 1] = v.y;
            xs[r * 65 + c4 + 2] = v.z;
            xs[r * 65 + c4 + 3] = v.w;
        }
        {
            const float4* Wg = (const float4*)(W + (size_t)kc * NHID);
            float4* Ws4 = (float4*)Ws;
#pragma unroll
            for (int it = 0; it < 8; it++)
                Ws4[tid + it * 128] = Wg[tid + it * 128];
        }
        __syncthreads();

#pragma unroll 4
        for (int k = 0; k < 64; k++) {
            float4 bb = *(const float4*)(Ws + k * 64 + cg);
#pragma unroll
            for (int i = 0; i < 8; i++) {
                float a = xs[(rg + i) * 65 + k];
                acc[i][0] += a * bb.x;
                acc[i][1] += a * bb.y;
                acc[i][2] += a * bb.z;
                acc[i][3] += a * bb.w;
            }
        }
        __syncthreads();
    }

#pragma unroll
    for (int i = 0; i < 8; i++) {
        int gr = row0 + rg + i;
        if (gr < N_NODES)
            *(float4*)(g_support + (size_t)gr * NHID + cg) =
                make_float4(acc[i][0], acc[i][1], acc[i][2], acc[i][3]);
    }
}

// ---------------------------------------------------------------------------
// K2: per-dst histogram: edge count + weighted degree.
// ---------------------------------------------------------------------------
__global__ __launch_bounds__(256) void k_hist(const void* __restrict__ ei,
                                              const float* __restrict__ ew) {
    int e = blockIdx.x * 256 + threadIdx.x;
    if (e < N_EDGES) {
        int dst = load_idx(ei, (size_t)N_EDGES + e);
        atomicAdd(&g_cnt[dst], 1);
        atomicAdd(&g_deg[dst], ew[e]);
    }
}

// ---------------------------------------------------------------------------
// K3a: per-block exclusive scan of cnt -> rowptr (block-local), block sums out.
// ---------------------------------------------------------------------------
__global__ __launch_bounds__(SCAN_BS) void k_scan1() {
    __shared__ int sh[SCAN_BS];
    int t = threadIdx.x;
    int i = blockIdx.x * SCAN_BS + t;
    int v = (i < N_NODES) ? g_cnt[i] : 0;
    sh[t] = v;
    __syncthreads();
#pragma unroll
    for (int off = 1; off < SCAN_BS; off <<= 1) {
        int add = (t >= off) ? sh[t - off] : 0;
        __syncthreads();
        sh[t] += add;
        __syncthreads();
    }
    if (i < N_NODES) g_rowptr[i] = sh[t] - v;          // exclusive
    if (t == SCAN_BS - 1) g_blksum[blockIdx.x] = sh[t];
}

// ---------------------------------------------------------------------------
// K3b: scan the block sums (single block).
// ---------------------------------------------------------------------------
__global__ __launch_bounds__(256) void k_scan2() {
    __shared__ int sh[256];
    int t = threadIdx.x;
    int v = (t < SCAN_BLOCKS) ? g_blksum[t] : 0;
    sh[t] = v;
    __syncthreads();
#pragma unroll
    for (int off = 1; off < 256; off <<= 1) {
        int add = (t >= off) ? sh[t - off] : 0;
        __syncthreads();
        sh[t] += add;
        __syncthreads();
    }
    if (t < SCAN_BLOCKS) g_blkoff[t] = sh[t] - v;      // exclusive
}

// ---------------------------------------------------------------------------
// K3c: finalize rowptr, init cursor, compute dinv.
// ---------------------------------------------------------------------------
__global__ __launch_bounds__(SCAN_BS) void k_scan3() {
    int i = blockIdx.x * SCAN_BS + threadIdx.x;
    if (i < N_NODES) {
        int rp = g_rowptr[i] + g_blkoff[blockIdx.x];
        g_rowptr[i] = rp;
        g_cursor[i] = rp;
        float d = g_deg[i];
        g_dinv[i] = (d > 0.0f) ? rsqrtf(d) : 0.0f;
    }
}

// ---------------------------------------------------------------------------
// K4: bin edges by dst: record {src, dinv[src]*w}.
// ---------------------------------------------------------------------------
__global__ __launch_bounds__(256) void k_bin(const void* __restrict__ ei,
                                             const float* __restrict__ ew) {
    int e = blockIdx.x * 256 + threadIdx.x;
    if (e < N_EDGES) {
        int src = load_idx(ei, e);
        int dst = load_idx(ei, (size_t)N_EDGES + e);
        float coef = g_dinv[src] * ew[e];
        int pos = atomicAdd(&g_cursor[dst], 1);
        g_bin[pos] = make_uint2((unsigned)src, __float_as_uint(coef));
    }
}

// ---------------------------------------------------------------------------
// K5: fused gather + bias + Student-t head. One warp per dst node.
// z[dst] = dinv[dst] * ( sum_e coef_e * support[src_e] + dinv[dst]*support[dst] ) + b
// ---------------------------------------------------------------------------
__global__ __launch_bounds__(256) void k_gather(const float* __restrict__ b,
                                                const float* __restrict__ mu,
                                                float* __restrict__ out) {
    __shared__ float smu[NCLUST * NHID];
    for (int i = threadIdx.x; i < NCLUST * NHID; i += 256)
        smu[i] = mu[i];
    __syncthreads();

    int node = blockIdx.x * 8 + (threadIdx.x >> 5);
    int lane = threadIdx.x & 31;
    if (node >= N_NODES) return;

    const float2* sup2 = (const float2*)g_support;
    float di = g_dinv[node];

    // self-loop term
    float2 s = sup2[(size_t)node * 32 + lane];
    float2 acc = make_float2(di * s.x, di * s.y);

    int start = g_rowptr[node];
    int cnt   = g_cnt[node];
    int k = 0;
    for (; k + 1 < cnt; k += 2) {                     // 2-way unroll for MLP
        uint2 e0 = g_bin[start + k];
        uint2 e1 = g_bin[start + k + 1];
        float2 s0 = sup2[(size_t)e0.x * 32 + lane];
        float2 s1 = sup2[(size_t)e1.x * 32 + lane];
        float c0 = __uint_as_float(e0.y);
        float c1 = __uint_as_float(e1.y);
        acc.x += c0 * s0.x + c1 * s1.x;
        acc.y += c0 * s0.y + c1 * s1.y;
    }
    if (k < cnt) {
        uint2 e0 = g_bin[start + k];
        float2 s0 = sup2[(size_t)e0.x * 32 + lane];
        float c0 = __uint_as_float(e0.y);
        acc.x += c0 * s0.x;
        acc.y += c0 * s0.y;
    }

    float2 bb = ((const float2*)b)[lane];
    float2 z = make_float2(di * acc.x + bb.x, di * acc.y + bb.y);
    ((float2*)out)[(size_t)node * 32 + lane] = z;

    // Student-t head
    float p[NCLUST];
#pragma unroll
    for (int c = 0; c < NCLUST; c++) {
        float dx = z.x - smu[c * NHID + 2 * lane];
        float dy = z.y - smu[c * NHID + 2 * lane + 1];
        p[c] = dx * dx + dy * dy;
    }
#pragma unroll
    for (int off = 16; off > 0; off >>= 1) {
#pragma unroll
        for (int c = 0; c < NCLUST; c++)
            p[c] += __shfl_xor_sync(0xffffffff, p[c], off);
    }
    float q[NCLUST];
    float qs = 0.0f;
#pragma unroll
    for (int c = 0; c < NCLUST; c++) {
        float t = 1.0f / (1.0f + p[c] * (1.0f / ALPHA) + 1e-8f);
        q[c] = __powf(t, ALPHA + 1.0f);   // /2 cancels under normalization
        qs += q[c];
    }
    float inv = 1.0f / qs;
    if (lane < NCLUST)
        out[(size_t)N_NODES * NHID + (size_t)node * NCLUST + lane] = q[lane] * inv;
}

// ---------------------------------------------------------------------------
extern "C" void kernel_launch(void* const* d_in, const int* in_sizes, int n_in,
                              void* d_out, int out_size) {
    const float* x  = (const float*)d_in[0];
    const void*  ei = d_in[1];
    const float* ew = (const float*)d_in[2];
    const float* W  = (const float*)d_in[3];
    const float* b  = (const float*)d_in[4];
    const float* mu = (const float*)d_in[5];
    float* out = (float*)d_out;

    k_detect<<<1, 1>>>(ei);
    k_gemm<<<(N_NODES + 63) / 64, 128>>>(x, W);
    k_hist<<<(N_EDGES + 255) / 256, 256>>>(ei, ew);
    k_scan1<<<SCAN_BLOCKS, SCAN_BS>>>();
    k_scan2<<<1, 256>>>();
    k_scan3<<<SCAN_BLOCKS, SCAN_BS>>>();
    k_bin<<<(N_EDGES + 255) / 256, 256>>>(ei, ew);
    k_gather<<<(N_NODES + 7) / 8, 256>>>(b, mu, out);
}